// round 5
// baseline (speedup 1.0000x reference)
#include <cuda_runtime.h>
#include <math.h>

#define BB 64
#define TT 2048
#define II 64
#define HH 128
#define OO 64
#define GG 384   // 3*H

// Scratch for x_proj [B, T, 3H] + 2 steps of padding (distance-2 prefetch
// reads up to t+2 unconditionally). __device__ global (no cudaMalloc allowed).
__device__ float g_xproj[(size_t)BB * TT * GG + 2 * GG];

typedef unsigned long long ull;

// Packed fp32x2 ops (Blackwell): elementwise on 2 floats.
__device__ __forceinline__ ull ffma2(ull a, ull b, ull c) {
    ull d;
    asm("fma.rn.f32x2 %0, %1, %2, %3;" : "=l"(d) : "l"(a), "l"(b), "l"(c));
    return d;
}
__device__ __forceinline__ ull fadd2(ull a, ull b) {
    ull d;
    asm("add.rn.f32x2 %0, %1, %2;" : "=l"(d) : "l"(a), "l"(b));
    return d;
}
__device__ __forceinline__ ull pack2(float lo, float hi) {
    ull d;
    asm("mov.b64 %0, {%1, %2};" : "=l"(d) : "f"(lo), "f"(hi));
    return d;
}
__device__ __forceinline__ float red2(ull a) {
    float x, y;
    asm("mov.b64 {%0,%1}, %2;" : "=f"(x), "=f"(y) : "l"(a));
    return x + y;
}

// Single-instruction MUFU.TANH (sm_75+), ~1e-5 abs error; GRU is a
// contraction so error stays ~1e-5 steady-state.
__device__ __forceinline__ float tanhap(float x) {
    float y;
    asm("tanh.approx.f32 %0, %1;" : "=f"(y) : "f"(x));
    return y;
}

// ---------------------------------------------------------------------------
// Kernel A: x_proj[b,t,g] = dot(x[b,t,:], W_ih[g,:]) + b_ih[g]
// Grid 2048: block = 64 rows; 128 threads, each owning THREE output columns
// (tid, 128+tid, 256+tid — one per gate). One broadcast LDS.128 of x feeds
// 6 FFMA2 (was 2): LDS wavefronts cut 3x -> FMA-bound.
// ---------------------------------------------------------------------------
__global__ void __launch_bounds__(128) xproj_kernel(
    const float* __restrict__ x, const float* __restrict__ W_ih,
    const float* __restrict__ b_ih)
{
    __shared__ __align__(16) float xs[64 * II];  // 16 KB, contiguous tile
    int tid = threadIdx.x;
    size_t row0 = (size_t)blockIdx.x * 64;

    {
        const float4* src = (const float4*)(x + row0 * II);
        float4* dst4 = (float4*)xs;
        for (int idx = tid; idx < 64 * II / 4; idx += 128) dst4[idx] = src[idx];
    }

    // Three W_ih rows in registers (192 regs).
    ull wr[II / 2], wz[II / 2], wn[II / 2];
    {
        const ulonglong2* pr = (const ulonglong2*)(W_ih + (size_t)tid * II);
        const ulonglong2* pz = (const ulonglong2*)(W_ih + (size_t)(HH + tid) * II);
        const ulonglong2* pn = (const ulonglong2*)(W_ih + (size_t)(2 * HH + tid) * II);
#pragma unroll
        for (int i = 0; i < II / 4; i++) {
            ulonglong2 vr = pr[i]; wr[2 * i] = vr.x; wr[2 * i + 1] = vr.y;
            ulonglong2 vz = pz[i]; wz[2 * i] = vz.x; wz[2 * i + 1] = vz.y;
            ulonglong2 vn = pn[i]; wn[2 * i] = vn.x; wn[2 * i + 1] = vn.y;
        }
    }
    float br = b_ih[tid], bz = b_ih[HH + tid], bn = b_ih[2 * HH + tid];
    __syncthreads();

    float* dst = g_xproj + row0 * GG + tid;
#pragma unroll 1
    for (int r = 0; r < 64; r++) {
        const ulonglong2* xp = (const ulonglong2*)(xs + r * II);
        ull ar0 = pack2(br, 0.0f), ar1 = 0ULL;
        ull az0 = pack2(bz, 0.0f), az1 = 0ULL;
        ull an0 = pack2(bn, 0.0f), an1 = 0ULL;
#pragma unroll
        for (int i = 0; i < II / 4; i++) {
            ulonglong2 v = xp[i];  // broadcast LDS.128: feeds 6 FFMA2
            ar0 = ffma2(wr[2 * i], v.x, ar0);
            ar1 = ffma2(wr[2 * i + 1], v.y, ar1);
            az0 = ffma2(wz[2 * i], v.x, az0);
            az1 = ffma2(wz[2 * i + 1], v.y, az1);
            an0 = ffma2(wn[2 * i], v.x, an0);
            an1 = ffma2(wn[2 * i + 1], v.y, an1);
        }
        float* drow = dst + (size_t)r * GG;
        __stcs(drow, red2(fadd2(ar0, ar1)));
        __stcs(drow + HH, red2(fadd2(az0, az1)));
        __stcs(drow + 2 * HH, red2(fadd2(an0, an1)));
    }
}

// ---------------------------------------------------------------------------
// Kernel B: GRU recurrence. One CTA per batch element, persistent over T.
// 384 threads: thread t owns row t of W_hh (128 weights in registers).
//  - r/z rows pre-scaled by 0.5 (exact) so sigmoid = 0.5+0.5*tanh(arg).
//  - Thread tid<128 keeps its own hr in-register and computes rg BEFORE
//    barrier 1 (off the serial chain). Only threads >=128 STS hg.
//  - Post-barrier chain: LDS hz/hn -> zg/ng (parallel TANH) -> hnew -> STS.
//  - latents store offloaded to threads 128..255 (store h(t-1) during the
//    dot phase of step t; race-free between bar2(t-1) and bar1(t)).
// ---------------------------------------------------------------------------
__global__ void __launch_bounds__(384, 1) gru_kernel(
    const float* __restrict__ W_hh, const float* __restrict__ b_hh,
    float* __restrict__ latents)
{
    __shared__ __align__(16) float h_s[HH];
    __shared__ float hg_s[GG];   // only [128..383] used

    int tid = threadIdx.x;
    int b = blockIdx.x;

    float scale = (tid < 2 * HH) ? 0.5f : 1.0f;  // r,z rows halved

    // W_hh row in registers (scaled), packed as 64 f32x2 pairs (128 regs).
    ull w2[HH / 2];
    {
        const float4* wp = (const float4*)(W_hh + (size_t)tid * HH);
#pragma unroll
        for (int i = 0; i < HH / 4; i++) {
            float4 v = wp[i];
            w2[2 * i] = pack2(v.x * scale, v.y * scale);
            w2[2 * i + 1] = pack2(v.z * scale, v.w * scale);
        }
    }
    float bias = b_hh[tid] * scale;

    const float* xbase = g_xproj + (size_t)b * TT * GG;
    float* latm = latents + (size_t)b * TT * HH + (tid - HH);  // store threads
    float* latbase = latents + (size_t)b * TT * HH;

    // Epilogue-thread (tid<128) register pipeline for gate x-values:
    // r,z pre-halved; n raw. Distance-2 prefetch.
    float xr0 = 0, xz0 = 0, xn0 = 0, xr1 = 0, xz1 = 0, xn1 = 0;
    if (tid < HH) {
        h_s[tid] = 0.0f;
        xr0 = 0.5f * xbase[tid];
        xz0 = 0.5f * xbase[HH + tid];
        xn0 = xbase[2 * HH + tid];
        xr1 = 0.5f * xbase[GG + tid];
        xz1 = 0.5f * xbase[GG + HH + tid];
        xn1 = xbase[GG + 2 * HH + tid];
    }
    const float* xq = xbase + 2 * GG;  // points at step t+2
    __syncthreads();

#pragma unroll 1
    for (int t = 0; t < TT; t++) {
        // Prefetch x-gates for step t+2 (padded region makes this safe).
        float pr = 0, pz = 0, pn = 0;
        if (tid < HH) {
            pr = 0.5f * xq[tid];
            pz = 0.5f * xq[HH + tid];
            pn = xq[2 * HH + tid];
        }
        xq += GG;

        // Offloaded latents store: h(t-1) is stable in h_s during this phase.
        if (t > 0 && tid >= HH && tid < 2 * HH) {
            __stcs(latm, h_s[tid - HH]);
            latm += HH;
        }

        // hg[row] = dot(W_hh_scaled[row,:], h) + bias  (4 chains of 16)
        ull a0 = pack2(bias, 0.0f), a1 = 0ULL, a2 = 0ULL, a3 = 0ULL;
        const ulonglong2* hp = (const ulonglong2*)h_s;
#pragma unroll
        for (int i = 0; i < HH / 8; i++) {
            ulonglong2 v0 = hp[2 * i];      // broadcast LDS.128
            ulonglong2 v1 = hp[2 * i + 1];
            a0 = ffma2(w2[4 * i], v0.x, a0);
            a1 = ffma2(w2[4 * i + 1], v0.y, a1);
            a2 = ffma2(w2[4 * i + 2], v1.x, a2);
            a3 = ffma2(w2[4 * i + 3], v1.y, a3);
        }
        float val = red2(fadd2(fadd2(a0, a1), fadd2(a2, a3)));

        float rg = 0.0f;
        if (tid < HH) {
            // hr is this thread's own dot result: rg computed pre-barrier.
            rg = 0.5f + 0.5f * tanhap(xr0 + val);
        } else {
            hg_s[tid] = val;
        }
        __syncthreads();

        if (tid < HH) {
            float hz = hg_s[HH + tid];
            float hn = hg_s[2 * HH + tid];
            float zg = 0.5f + 0.5f * tanhap(xz0 + hz);
            float ng = tanhap(fmaf(rg, hn, xn0));
            float hnew = fmaf(zg, h_s[tid] - ng, ng);
            h_s[tid] = hnew;
        }
        xr0 = xr1; xz0 = xz1; xn0 = xn1;
        xr1 = pr;  xz1 = pz;  xn1 = pn;
        __syncthreads();
    }

    // Final latents row: h(T-1) (bar above guarantees h_s final).
    if (tid >= HH && tid < 2 * HH)
        __stcs(latbase + (size_t)(TT - 1) * HH + (tid - HH), h_s[tid - HH]);
}

// ---------------------------------------------------------------------------
// Kernel C: output[b,t,o] = dot(latents[b,t,:], W_out[o,:]) + b_out[o]
// (unchanged this round for attribution)
// ---------------------------------------------------------------------------
__global__ void __launch_bounds__(256) out_kernel(
    const float* __restrict__ latents, const float* __restrict__ W_out,
    const float* __restrict__ b_out, float* __restrict__ out)
{
    __shared__ __align__(16) float lt[64 * HH];  // 32 KB
    int tid = threadIdx.x;
    size_t row0 = (size_t)blockIdx.x * 64;

    {
        const float4* src = (const float4*)(latents + row0 * HH);
        float4* dst = (float4*)lt;
        for (int idx = tid; idx < 64 * HH / 4; idx += 256) dst[idx] = src[idx];
    }

    int o = tid & 63;
    int q = tid >> 6;  // 0..3 -> 16 rows each

    ull w2[HH / 2];
    {
        const ulonglong2* wp = (const ulonglong2*)(W_out + (size_t)o * HH);
#pragma unroll
        for (int i = 0; i < HH / 4; i++) {
            ulonglong2 v = wp[i];
            w2[2 * i] = v.x; w2[2 * i + 1] = v.y;
        }
    }
    float bias = b_out[o];
    __syncthreads();

#pragma unroll 1
    for (int j = 0; j < 16; j += 2) {
        int r = q * 16 + j;
        const ulonglong2* lpa = (const ulonglong2*)(lt + r * HH);
        const ulonglong2* lpb = (const ulonglong2*)(lt + (r + 1) * HH);
        ull a0 = pack2(bias, 0.0f), a1 = 0ULL;
        ull b0 = pack2(bias, 0.0f), b1 = 0ULL;
#pragma unroll
        for (int i = 0; i < HH / 4; i++) {
            ulonglong2 va = lpa[i];  // broadcast LDS.128
            ulonglong2 vb = lpb[i];
            a0 = ffma2(w2[2 * i], va.x, a0);
            a1 = ffma2(w2[2 * i + 1], va.y, a1);
            b0 = ffma2(w2[2 * i], vb.x, b0);
            b1 = ffma2(w2[2 * i + 1], vb.y, b1);
        }
        __stcs(out + (row0 + r) * OO + o, red2(fadd2(a0, a1)));
        __stcs(out + (row0 + r + 1) * OO + o, red2(fadd2(b0, b1)));
    }
}

// ---------------------------------------------------------------------------
extern "C" void kernel_launch(void* const* d_in, const int* in_sizes, int n_in,
                              void* d_out, int out_size) {
    const float* x     = (const float*)d_in[0];
    const float* W_ih  = (const float*)d_in[1];
    const float* W_hh  = (const float*)d_in[2];
    const float* b_ih  = (const float*)d_in[3];
    const float* b_hh  = (const float*)d_in[4];
    const float* W_out = (const float*)d_in[5];
    const float* b_out = (const float*)d_in[6];

    float* out = (float*)d_out;                        // [B,T,O] first
    float* latents = out + (size_t)BB * TT * OO;       // then [B,T,H]

    xproj_kernel<<<(BB * TT) / 64, 128>>>(x, W_ih, b_ih);
    gru_kernel<<<BB, 384>>>(W_hh, b_hh, latents);
    out_kernel<<<(BB * TT) / 64, 256>>>(latents, W_out, b_out, out);
}

// round 6
// speedup vs baseline: 1.1179x; 1.1179x over previous
#include <cuda_runtime.h>
#include <math.h>

#define BB 64
#define TT 2048
#define II 64
#define HH 128
#define OO 64
#define GG 384   // 3*H

// Scratch for x_proj [B, T, 3H] + 2 steps of padding (distance-2 prefetch
// reads up to t+2 unconditionally). __device__ global (no cudaMalloc allowed).
__device__ float g_xproj[(size_t)BB * TT * GG + 2 * GG];

typedef unsigned long long ull;

// Packed fp32x2 ops (Blackwell): elementwise on 2 floats.
__device__ __forceinline__ ull ffma2(ull a, ull b, ull c) {
    ull d;
    asm("fma.rn.f32x2 %0, %1, %2, %3;" : "=l"(d) : "l"(a), "l"(b), "l"(c));
    return d;
}
__device__ __forceinline__ ull fadd2(ull a, ull b) {
    ull d;
    asm("add.rn.f32x2 %0, %1, %2;" : "=l"(d) : "l"(a), "l"(b));
    return d;
}
__device__ __forceinline__ ull pack2(float lo, float hi) {
    ull d;
    asm("mov.b64 %0, {%1, %2};" : "=l"(d) : "f"(lo), "f"(hi));
    return d;
}
__device__ __forceinline__ float red2(ull a) {
    float x, y;
    asm("mov.b64 {%0,%1}, %2;" : "=f"(x), "=f"(y) : "l"(a));
    return x + y;
}

// Single-instruction MUFU.TANH (sm_75+), ~1e-5 abs error; GRU is a
// contraction so error stays ~1e-5 steady-state.
__device__ __forceinline__ float tanhap(float x) {
    float y;
    asm("tanh.approx.f32 %0, %1;" : "=f"(y) : "f"(x));
    return y;
}
__device__ __forceinline__ float sigmap(float x) {
    return 0.5f + 0.5f * tanhap(0.5f * x);
}

// ---------------------------------------------------------------------------
// Kernel A: x_proj[b,t,g] = dot(x[b,t,:], W_ih[g,:]) + b_ih[g]
// Grid 2048: block = 64 rows; 128 threads, each owning THREE output columns
// (tid, 128+tid, 256+tid — one per gate). One broadcast LDS.128 of x feeds
// 6 FFMA2: LDS wavefronts cut 3x -> FMA-bound. (R5 version, kept.)
// ---------------------------------------------------------------------------
__global__ void __launch_bounds__(128) xproj_kernel(
    const float* __restrict__ x, const float* __restrict__ W_ih,
    const float* __restrict__ b_ih)
{
    __shared__ __align__(16) float xs[64 * II];  // 16 KB, contiguous tile
    int tid = threadIdx.x;
    size_t row0 = (size_t)blockIdx.x * 64;

    {
        const float4* src = (const float4*)(x + row0 * II);
        float4* dst4 = (float4*)xs;
        for (int idx = tid; idx < 64 * II / 4; idx += 128) dst4[idx] = src[idx];
    }

    // Three W_ih rows in registers (192 regs).
    ull wr[II / 2], wz[II / 2], wn[II / 2];
    {
        const ulonglong2* pr = (const ulonglong2*)(W_ih + (size_t)tid * II);
        const ulonglong2* pz = (const ulonglong2*)(W_ih + (size_t)(HH + tid) * II);
        const ulonglong2* pn = (const ulonglong2*)(W_ih + (size_t)(2 * HH + tid) * II);
#pragma unroll
        for (int i = 0; i < II / 4; i++) {
            ulonglong2 vr = pr[i]; wr[2 * i] = vr.x; wr[2 * i + 1] = vr.y;
            ulonglong2 vz = pz[i]; wz[2 * i] = vz.x; wz[2 * i + 1] = vz.y;
            ulonglong2 vn = pn[i]; wn[2 * i] = vn.x; wn[2 * i + 1] = vn.y;
        }
    }
    float br = b_ih[tid], bz = b_ih[HH + tid], bn = b_ih[2 * HH + tid];
    __syncthreads();

    float* dst = g_xproj + row0 * GG + tid;
#pragma unroll 1
    for (int r = 0; r < 64; r++) {
        const ulonglong2* xp = (const ulonglong2*)(xs + r * II);
        ull ar0 = pack2(br, 0.0f), ar1 = 0ULL;
        ull az0 = pack2(bz, 0.0f), az1 = 0ULL;
        ull an0 = pack2(bn, 0.0f), an1 = 0ULL;
#pragma unroll
        for (int i = 0; i < II / 4; i++) {
            ulonglong2 v = xp[i];  // broadcast LDS.128: feeds 6 FFMA2
            ar0 = ffma2(wr[2 * i], v.x, ar0);
            ar1 = ffma2(wr[2 * i + 1], v.y, ar1);
            az0 = ffma2(wz[2 * i], v.x, az0);
            az1 = ffma2(wz[2 * i + 1], v.y, az1);
            an0 = ffma2(wn[2 * i], v.x, an0);
            an1 = ffma2(wn[2 * i + 1], v.y, an1);
        }
        float* drow = dst + (size_t)r * GG;
        __stcs(drow, red2(fadd2(ar0, ar1)));
        __stcs(drow + HH, red2(fadd2(az0, az1)));
        __stcs(drow + 2 * HH, red2(fadd2(an0, an1)));
    }
}

// ---------------------------------------------------------------------------
// Kernel B: GRU recurrence (R4 structure + rg-pre-barrier only).
// One CTA per batch element, persistent over T. 384 threads: thread t owns
// row t of W_hh (128 weights in registers, plain ulonglong2 load — no
// repacking, no scaling). h in SMEM (broadcast LDS.128), 4 accum chains.
// Thread tid<128 owns hr = its own dot result: rg computed BEFORE barrier 1.
// Epilogue (tid<128): LDS hz/hn -> 2 independent TANH -> hnew -> STS + STG.
// ---------------------------------------------------------------------------
__global__ void __launch_bounds__(384, 1) gru_kernel(
    const float* __restrict__ W_hh, const float* __restrict__ b_hh,
    float* __restrict__ latents)
{
    __shared__ __align__(16) float h_s[HH];
    __shared__ float hg_s[GG];   // only [128..383] used

    int tid = threadIdx.x;
    int b = blockIdx.x;

    // W_hh row in registers, packed as 64 f32x2 pairs (128 regs).
    ull w2[HH / 2];
    {
        const ulonglong2* wp = (const ulonglong2*)(W_hh + (size_t)tid * HH);
#pragma unroll
        for (int i = 0; i < HH / 4; i++) {
            ulonglong2 v = wp[i];
            w2[2 * i] = v.x; w2[2 * i + 1] = v.y;
        }
    }
    float bias = b_hh[tid];

    const float* xbase = g_xproj + (size_t)b * TT * GG;
    float* lat = latents + (size_t)b * TT * HH + tid;

    // Epilogue-thread (tid<128) register pipeline for gate x-values,
    // distance-2 prefetch.
    float xr0 = 0, xz0 = 0, xn0 = 0, xr1 = 0, xz1 = 0, xn1 = 0;
    if (tid < HH) {
        h_s[tid] = 0.0f;
        xr0 = xbase[tid];           xz0 = xbase[HH + tid];      xn0 = xbase[2 * HH + tid];
        xr1 = xbase[GG + tid];      xz1 = xbase[GG + HH + tid]; xn1 = xbase[GG + 2 * HH + tid];
    }
    const float* xq = xbase + 2 * GG;  // points at step t+2
    __syncthreads();

#pragma unroll 1
    for (int t = 0; t < TT; t++) {
        // Prefetch x-gates for step t+2 (padded region makes this safe).
        float pr = 0, pz = 0, pn = 0;
        if (tid < HH) {
            pr = xq[tid]; pz = xq[HH + tid]; pn = xq[2 * HH + tid];
        }
        xq += GG;

        // hg[row] = dot(W_hh[row,:], h) + b_hh[row]  (4 chains of 16)
        ull a0 = pack2(bias, 0.0f), a1 = 0ULL, a2 = 0ULL, a3 = 0ULL;
        const ulonglong2* hp = (const ulonglong2*)h_s;
#pragma unroll
        for (int i = 0; i < HH / 8; i++) {
            ulonglong2 v0 = hp[2 * i];      // broadcast LDS.128
            ulonglong2 v1 = hp[2 * i + 1];
            a0 = ffma2(w2[4 * i], v0.x, a0);
            a1 = ffma2(w2[4 * i + 1], v0.y, a1);
            a2 = ffma2(w2[4 * i + 2], v1.x, a2);
            a3 = ffma2(w2[4 * i + 3], v1.y, a3);
        }
        float val = red2(fadd2(fadd2(a0, a1), fadd2(a2, a3)));

        float rg = 0.0f;
        if (tid < HH) {
            // hr is this thread's own dot result: rg computed pre-barrier,
            // off the post-barrier serial chain.
            rg = sigmap(xr0 + val);
        } else {
            hg_s[tid] = val;
        }
        __syncthreads();

        if (tid < HH) {
            float hz = hg_s[HH + tid];
            float hn = hg_s[2 * HH + tid];
            float zg = sigmap(xz0 + hz);                 // TANH chain A
            float ng = tanhap(fmaf(rg, hn, xn0));        // TANH chain B (indep)
            float hnew = fmaf(zg, h_s[tid] - ng, ng);
            h_s[tid] = hnew;
            __stcs(lat, hnew);
        }
        lat += HH;
        xr0 = xr1; xz0 = xz1; xn0 = xn1;
        xr1 = pr;  xz1 = pz;  xn1 = pn;
        __syncthreads();
    }
}

// ---------------------------------------------------------------------------
// Kernel C: output[b,t,o] = dot(latents[b,t,:], W_out[o,:]) + b_out[o]
// (unchanged for attribution)
// ---------------------------------------------------------------------------
__global__ void __launch_bounds__(256) out_kernel(
    const float* __restrict__ latents, const float* __restrict__ W_out,
    const float* __restrict__ b_out, float* __restrict__ out)
{
    __shared__ __align__(16) float lt[64 * HH];  // 32 KB
    int tid = threadIdx.x;
    size_t row0 = (size_t)blockIdx.x * 64;

    {
        const float4* src = (const float4*)(latents + row0 * HH);
        float4* dst = (float4*)lt;
        for (int idx = tid; idx < 64 * HH / 4; idx += 256) dst[idx] = src[idx];
    }

    int o = tid & 63;
    int q = tid >> 6;  // 0..3 -> 16 rows each

    ull w2[HH / 2];
    {
        const ulonglong2* wp = (const ulonglong2*)(W_out + (size_t)o * HH);
#pragma unroll
        for (int i = 0; i < HH / 4; i++) {
            ulonglong2 v = wp[i];
            w2[2 * i] = v.x; w2[2 * i + 1] = v.y;
        }
    }
    float bias = b_out[o];
    __syncthreads();

#pragma unroll 1
    for (int j = 0; j < 16; j += 2) {
        int r = q * 16 + j;
        const ulonglong2* lpa = (const ulonglong2*)(lt + r * HH);
        const ulonglong2* lpb = (const ulonglong2*)(lt + (r + 1) * HH);
        ull a0 = pack2(bias, 0.0f), a1 = 0ULL;
        ull b0 = pack2(bias, 0.0f), b1 = 0ULL;
#pragma unroll
        for (int i = 0; i < HH / 4; i++) {
            ulonglong2 va = lpa[i];  // broadcast LDS.128
            ulonglong2 vb = lpb[i];
            a0 = ffma2(w2[2 * i], va.x, a0);
            a1 = ffma2(w2[2 * i + 1], va.y, a1);
            b0 = ffma2(w2[2 * i], vb.x, b0);
            b1 = ffma2(w2[2 * i + 1], vb.y, b1);
        }
        __stcs(out + (row0 + r) * OO + o, red2(fadd2(a0, a1)));
        __stcs(out + (row0 + r + 1) * OO + o, red2(fadd2(b0, b1)));
    }
}

// ---------------------------------------------------------------------------
extern "C" void kernel_launch(void* const* d_in, const int* in_sizes, int n_in,
                              void* d_out, int out_size) {
    const float* x     = (const float*)d_in[0];
    const float* W_ih  = (const float*)d_in[1];
    const float* W_hh  = (const float*)d_in[2];
    const float* b_ih  = (const float*)d_in[3];
    const float* b_hh  = (const float*)d_in[4];
    const float* W_out = (const float*)d_in[5];
    const float* b_out = (const float*)d_in[6];

    float* out = (float*)d_out;                        // [B,T,O] first
    float* latents = out + (size_t)BB * TT * OO;       // then [B,T,H]

    xproj_kernel<<<(BB * TT) / 64, 128>>>(x, W_ih, b_ih);
    gru_kernel<<<BB, 384>>>(W_hh, b_hh, latents);
    out_kernel<<<(BB * TT) / 64, 256>>>(latents, W_out, b_out, out);
}

// round 7
// speedup vs baseline: 1.1918x; 1.0662x over previous
#include <cuda_runtime.h>
#include <math.h>

#define BB 64
#define TT 2048
#define II 64
#define HH 128
#define OO 64
#define GG 384   // 3*H

// Scratch for x_proj [B, T, 3H] + 2 steps of padding (distance-2 prefetch
// reads up to t+2 unconditionally). __device__ global (no cudaMalloc allowed).
__device__ float g_xproj[(size_t)BB * TT * GG + 2 * GG];

typedef unsigned long long ull;

// Packed fp32x2 ops (Blackwell): elementwise on 2 floats.
__device__ __forceinline__ ull ffma2(ull a, ull b, ull c) {
    ull d;
    asm("fma.rn.f32x2 %0, %1, %2, %3;" : "=l"(d) : "l"(a), "l"(b), "l"(c));
    return d;
}
__device__ __forceinline__ ull fadd2(ull a, ull b) {
    ull d;
    asm("add.rn.f32x2 %0, %1, %2;" : "=l"(d) : "l"(a), "l"(b));
    return d;
}
__device__ __forceinline__ ull pack2(float lo, float hi) {
    ull d;
    asm("mov.b64 %0, {%1, %2};" : "=l"(d) : "f"(lo), "f"(hi));
    return d;
}
__device__ __forceinline__ float red2(ull a) {
    float x, y;
    asm("mov.b64 {%0,%1}, %2;" : "=f"(x), "=f"(y) : "l"(a));
    return x + y;
}

// Single-instruction MUFU.TANH (sm_75+), ~1e-5 abs error; GRU is a
// contraction so error stays ~1e-5 steady-state.
__device__ __forceinline__ float tanhap(float x) {
    float y;
    asm("tanh.approx.f32 %0, %1;" : "=f"(y) : "f"(x));
    return y;
}
__device__ __forceinline__ float sigmap(float x) {
    return 0.5f + 0.5f * tanhap(0.5f * x);
}

// ---------------------------------------------------------------------------
// Kernel A: x_proj (R5/R6 version, kept — 198 us, fma 47%).
// ---------------------------------------------------------------------------
__global__ void __launch_bounds__(128) xproj_kernel(
    const float* __restrict__ x, const float* __restrict__ W_ih,
    const float* __restrict__ b_ih)
{
    __shared__ __align__(16) float xs[64 * II];  // 16 KB, contiguous tile
    int tid = threadIdx.x;
    size_t row0 = (size_t)blockIdx.x * 64;

    {
        const float4* src = (const float4*)(x + row0 * II);
        float4* dst4 = (float4*)xs;
        for (int idx = tid; idx < 64 * II / 4; idx += 128) dst4[idx] = src[idx];
    }

    // Three W_ih rows in registers (192 regs).
    ull wr[II / 2], wz[II / 2], wn[II / 2];
    {
        const ulonglong2* pr = (const ulonglong2*)(W_ih + (size_t)tid * II);
        const ulonglong2* pz = (const ulonglong2*)(W_ih + (size_t)(HH + tid) * II);
        const ulonglong2* pn = (const ulonglong2*)(W_ih + (size_t)(2 * HH + tid) * II);
#pragma unroll
        for (int i = 0; i < II / 4; i++) {
            ulonglong2 vr = pr[i]; wr[2 * i] = vr.x; wr[2 * i + 1] = vr.y;
            ulonglong2 vz = pz[i]; wz[2 * i] = vz.x; wz[2 * i + 1] = vz.y;
            ulonglong2 vn = pn[i]; wn[2 * i] = vn.x; wn[2 * i + 1] = vn.y;
        }
    }
    float br = b_ih[tid], bz = b_ih[HH + tid], bn = b_ih[2 * HH + tid];
    __syncthreads();

    float* dst = g_xproj + row0 * GG + tid;
#pragma unroll 1
    for (int r = 0; r < 64; r++) {
        const ulonglong2* xp = (const ulonglong2*)(xs + r * II);
        ull ar0 = pack2(br, 0.0f), ar1 = 0ULL;
        ull az0 = pack2(bz, 0.0f), az1 = 0ULL;
        ull an0 = pack2(bn, 0.0f), an1 = 0ULL;
#pragma unroll
        for (int i = 0; i < II / 4; i++) {
            ulonglong2 v = xp[i];  // broadcast LDS.128: feeds 6 FFMA2
            ar0 = ffma2(wr[2 * i], v.x, ar0);
            ar1 = ffma2(wr[2 * i + 1], v.y, ar1);
            az0 = ffma2(wz[2 * i], v.x, az0);
            az1 = ffma2(wz[2 * i + 1], v.y, az1);
            an0 = ffma2(wn[2 * i], v.x, an0);
            an1 = ffma2(wn[2 * i + 1], v.y, an1);
        }
        float* drow = dst + (size_t)r * GG;
        __stcs(drow, red2(fadd2(ar0, ar1)));
        __stcs(drow + HH, red2(fadd2(az0, az1)));
        __stcs(drow + 2 * HH, red2(fadd2(an0, an1)));
    }
}

// ---------------------------------------------------------------------------
// Kernel B: GRU recurrence — gate math distributed across warp groups.
//  thread tid owns W_hh row tid (128 weights in regs).
//  Pre-barrier:  r-threads (0..127)  compute rg (keep in REGISTER, no STS)
//                z-threads (128..255) compute zg -> STS hg_s[tid]
//                n-threads (256..383) STS raw hn  -> hg_s[tid]
//  Post-barrier (r-threads only): LDS zg,hn -> ng=tanh(fma(rg,hn,xn))
//                -> hnew = ng + zg*(hprev-ng)  (hprev in register)
//  Prefetch (distance 2): every thread<256 loads its OWN gate x value
//  (xbase[..+tid]); r-threads additionally load xn (xbase[..+2H+tid]).
// ---------------------------------------------------------------------------
__global__ void __launch_bounds__(384, 1) gru_kernel(
    const float* __restrict__ W_hh, const float* __restrict__ b_hh,
    float* __restrict__ latents)
{
    __shared__ __align__(16) float h_s[HH];
    __shared__ float hg_s[GG];   // [128..255]=zg, [256..383]=hn

    int tid = threadIdx.x;
    int b = blockIdx.x;

    // W_hh row in registers, packed as 64 f32x2 pairs (128 regs).
    ull w2[HH / 2];
    {
        const ulonglong2* wp = (const ulonglong2*)(W_hh + (size_t)tid * HH);
#pragma unroll
        for (int i = 0; i < HH / 4; i++) {
            ulonglong2 v = wp[i];
            w2[2 * i] = v.x; w2[2 * i + 1] = v.y;
        }
    }
    float bias = b_hh[tid];

    const float* xbase = g_xproj + (size_t)b * TT * GG;
    float* lat = latents + (size_t)b * TT * HH + tid;

    // Distance-2 prefetch pipeline. xg: own-gate value (threads < 256);
    // xn: n-gate value (r-threads only). hprev: h in register (r-threads).
    float xg0 = 0, xg1 = 0, xn0 = 0, xn1 = 0, hprev = 0.0f;
    if (tid < HH) h_s[tid] = 0.0f;
    if (tid < 2 * HH) {
        xg0 = xbase[tid];
        xg1 = xbase[GG + tid];
    }
    if (tid < HH) {
        xn0 = xbase[2 * HH + tid];
        xn1 = xbase[GG + 2 * HH + tid];
    }
    const float* xq = xbase + 2 * GG + tid;  // own column at step t+2
    __syncthreads();

#pragma unroll 1
    for (int t = 0; t < TT; t++) {
        // Prefetch for step t+2 (padded region makes this safe).
        float pg = 0, pn = 0;
        if (tid < 2 * HH) pg = xq[0];
        if (tid < HH) pn = xq[2 * HH];
        xq += GG;

        // hg[row] = dot(W_hh[row,:], h) + b_hh[row]  (4 chains of 16)
        ull a0 = pack2(bias, 0.0f), a1 = 0ULL, a2 = 0ULL, a3 = 0ULL;
        const ulonglong2* hp = (const ulonglong2*)h_s;
#pragma unroll
        for (int i = 0; i < HH / 8; i++) {
            ulonglong2 v0 = hp[2 * i];      // broadcast LDS.128
            ulonglong2 v1 = hp[2 * i + 1];
            a0 = ffma2(w2[4 * i], v0.x, a0);
            a1 = ffma2(w2[4 * i + 1], v0.y, a1);
            a2 = ffma2(w2[4 * i + 2], v1.x, a2);
            a3 = ffma2(w2[4 * i + 3], v1.y, a3);
        }
        float val = red2(fadd2(fadd2(a0, a1), fadd2(a2, a3)));

        // Pre-barrier gate work, distributed by warp group.
        float rg = 0.0f;
        if (tid < HH) {
            rg = sigmap(xg0 + val);          // stays in register
        } else if (tid < 2 * HH) {
            hg_s[tid] = sigmap(xg0 + val);   // zg
        } else {
            hg_s[tid] = val;                 // hn (raw)
        }
        __syncthreads();

        if (tid < HH) {
            float zg = hg_s[HH + tid];
            float hn = hg_s[2 * HH + tid];
            float ng = tanhap(fmaf(rg, hn, xn0));
            float hnew = fmaf(zg, hprev - ng, ng);
            h_s[tid] = hnew;
            hprev = hnew;
            __stcs(lat, hnew);
        }
        lat += HH;
        xg0 = xg1; xg1 = pg;
        xn0 = xn1; xn1 = pn;
        __syncthreads();
    }
}

// ---------------------------------------------------------------------------
// Kernel C: output GEMM (unchanged for attribution).
// ---------------------------------------------------------------------------
__global__ void __launch_bounds__(256) out_kernel(
    const float* __restrict__ latents, const float* __restrict__ W_out,
    const float* __restrict__ b_out, float* __restrict__ out)
{
    __shared__ __align__(16) float lt[64 * HH];  // 32 KB
    int tid = threadIdx.x;
    size_t row0 = (size_t)blockIdx.x * 64;

    {
        const float4* src = (const float4*)(latents + row0 * HH);
        float4* dst = (float4*)lt;
        for (int idx = tid; idx < 64 * HH / 4; idx += 256) dst[idx] = src[idx];
    }

    int o = tid & 63;
    int q = tid >> 6;  // 0..3 -> 16 rows each

    ull w2[HH / 2];
    {
        const ulonglong2* wp = (const ulonglong2*)(W_out + (size_t)o * HH);
#pragma unroll
        for (int i = 0; i < HH / 4; i++) {
            ulonglong2 v = wp[i];
            w2[2 * i] = v.x; w2[2 * i + 1] = v.y;
        }
    }
    float bias = b_out[o];
    __syncthreads();

#pragma unroll 1
    for (int j = 0; j < 16; j += 2) {
        int r = q * 16 + j;
        const ulonglong2* lpa = (const ulonglong2*)(lt + r * HH);
        const ulonglong2* lpb = (const ulonglong2*)(lt + (r + 1) * HH);
        ull a0 = pack2(bias, 0.0f), a1 = 0ULL;
        ull b0 = pack2(bias, 0.0f), b1 = 0ULL;
#pragma unroll
        for (int i = 0; i < HH / 4; i++) {
            ulonglong2 va = lpa[i];  // broadcast LDS.128
            ulonglong2 vb = lpb[i];
            a0 = ffma2(w2[2 * i], va.x, a0);
            a1 = ffma2(w2[2 * i + 1], va.y, a1);
            b0 = ffma2(w2[2 * i], vb.x, b0);
            b1 = ffma2(w2[2 * i + 1], vb.y, b1);
        }
        __stcs(out + (row0 + r) * OO + o, red2(fadd2(a0, a1)));
        __stcs(out + (row0 + r + 1) * OO + o, red2(fadd2(b0, b1)));
    }
}

// ---------------------------------------------------------------------------
extern "C" void kernel_launch(void* const* d_in, const int* in_sizes, int n_in,
                              void* d_out, int out_size) {
    const float* x     = (const float*)d_in[0];
    const float* W_ih  = (const float*)d_in[1];
    const float* W_hh  = (const float*)d_in[2];
    const float* b_ih  = (const float*)d_in[3];
    const float* b_hh  = (const float*)d_in[4];
    const float* W_out = (const float*)d_in[5];
    const float* b_out = (const float*)d_in[6];

    float* out = (float*)d_out;                        // [B,T,O] first
    float* latents = out + (size_t)BB * TT * OO;       // then [B,T,H]

    xproj_kernel<<<(BB * TT) / 64, 128>>>(x, W_ih, b_ih);
    gru_kernel<<<BB, 384>>>(W_hh, b_hh, latents);
    out_kernel<<<(BB * TT) / 64, 256>>>(latents, W_out, b_out, out);
}